// round 14
// baseline (speedup 1.0000x reference)
#include <cuda_runtime.h>
#include <cuda_bf16.h>
#include <cstdint>

typedef unsigned long long ull;
typedef unsigned int u32;

#define HDIM 1024
#define BDIM 64
#define TSTEPS 512
#define NCTA 128
#define NB 8
#define RTHREADS 384              // warps 0-7 consumers (1 chunk each), 8-11 producers
#define KCH 128
#define NCHUNK 8
#define NTOT (TSTEPS * NCHUNK)

// recur smem (relative to 1024B-aligned base)
#define OFF_WHI 0
#define OFF_WLO 49152
#define OFF_RING 98304             // 3 slots x 32768 (hi 16K + lo 16K)
#define SLOT_SZ 32768
#define OFF_D   196608             // 4 buffers x 64x26 floats = 26624
#define SMEM_USED (196608 + 26624)
#define SMEM_TOTAL (SMEM_USED + 1024)
#define DS_STRIDE 26
#define DSZ (64 * DS_STRIDE)

// xa smem per buffer: Ahi 16K | Alo 16K | Bhi 8K | Blo 8K
#define XA_ALO 16384
#define XA_BHI 32768
#define XA_BLO 40960
#define XA_BUF 49152
#define XA_SMEM (2 * XA_BUF + 1024)

__device__ float g_A[(size_t)TSTEPS * BDIM * HDIM];          // [T][B][H]
__device__ __nv_bfloat16 g_xh[(size_t)BDIM * TSTEPS * HDIM];
__device__ __nv_bfloat16 g_xl[(size_t)BDIM * TSTEPS * HDIM];
__device__ __nv_bfloat16 g_wh[HDIM * HDIM];
__device__ __nv_bfloat16 g_wl[HDIM * HDIM];
__device__ __nv_bfloat16 g_hh[2][BDIM * HDIM];
__device__ __nv_bfloat16 g_hl[2][BDIM * HDIM];
__device__ u32 g_ready[8][32];                               // one 128B line per counter

// ---------------- helpers ----------------
__device__ __forceinline__ u32 smem_u32(const void* p) {
    u32 a;
    asm("{ .reg .u64 t; cvta.to.shared.u64 t, %1; cvt.u32.u64 %0, t; }" : "=r"(a) : "l"(p));
    return a;
}
__device__ __forceinline__ void ldsm_x4(u32 a, u32& r0, u32& r1, u32& r2, u32& r3) {
    asm volatile("ldmatrix.sync.aligned.m8n8.x4.shared.b16 {%0,%1,%2,%3}, [%4];"
                 : "=r"(r0), "=r"(r1), "=r"(r2), "=r"(r3) : "r"(a));
}
__device__ __forceinline__ void ldsm_x2(u32 a, u32& r0, u32& r1) {
    asm volatile("ldmatrix.sync.aligned.m8n8.x2.shared.b16 {%0,%1}, [%2];"
                 : "=r"(r0), "=r"(r1) : "r"(a));
}
__device__ __forceinline__ void mma_bf16(float* c, u32 a0, u32 a1, u32 a2, u32 a3, u32 b0, u32 b1) {
    asm volatile(
        "mma.sync.aligned.m16n8k16.row.col.f32.bf16.bf16.f32 "
        "{%0,%1,%2,%3}, {%4,%5,%6,%7}, {%8,%9}, {%0,%1,%2,%3};"
        : "+f"(c[0]), "+f"(c[1]), "+f"(c[2]), "+f"(c[3])
        : "r"(a0), "r"(a1), "r"(a2), "r"(a3), "r"(b0), "r"(b1));
}
__device__ __forceinline__ void cpa16(u32 d, const void* s) {
    asm volatile("cp.async.cg.shared.global [%0], [%1], 16;" :: "r"(d), "l"(s) : "memory");
}
#define CP_COMMIT() asm volatile("cp.async.commit_group;" ::: "memory")
#define CP_WAIT0()  asm volatile("cp.async.wait_group 0;" ::: "memory")
#define CP_WAIT1()  asm volatile("cp.async.wait_group 1;" ::: "memory")
__device__ __forceinline__ void bar_sync_id(int id, int cnt) {
    asm volatile("bar.sync %0, %1;" :: "r"(id), "r"(cnt) : "memory");
}
__device__ __forceinline__ void bar_arrive_id(int id, int cnt) {
    asm volatile("bar.arrive %0, %1;" :: "r"(id), "r"(cnt) : "memory");
}
__device__ __forceinline__ unsigned short f2bf(float f) { return __bfloat16_as_ushort(__float2bfloat16(f)); }
__device__ __forceinline__ float bf2f(unsigned short s) { return __bfloat162float(__ushort_as_bfloat16(s)); }
__device__ __forceinline__ float sigf(float x) { return 1.0f / (1.0f + __expf(-x)); }
__device__ __forceinline__ u32 ld_acq(const u32* p) {
    u32 v;
    asm volatile("ld.acquire.gpu.global.u32 %0, [%1];" : "=r"(v) : "l"(p) : "memory");
    return v;
}
__device__ __forceinline__ void red_rel(u32* p) {
    asm volatile("red.release.gpu.global.add.u32 [%0], %1;" :: "l"(p), "r"(1u) : "memory");
}
__device__ __forceinline__ void wait_cnt_w(int c, u32 need, int lane) {
    if (lane == 0) {
        const u32* p = &g_ready[c][0];
        while (ld_acq(p) < need) { __nanosleep(40); }
    }
    __syncwarp();
}
__device__ __forceinline__ u32 swz64(int row, int k) {   // 64-col bf16 tile, 128B rows
    u32 b = (u32)(row >> 3) * 1024u + (u32)(row & 7) * 128u + (u32)(k & 63) * 2u;
    return b ^ ((u32)(row & 7) << 4);
}
__device__ __forceinline__ u32 swzA(int row, int k) {    // A tile [64 rows][128 k]
    u32 b = (u32)(k >> 6) * 8192u + (u32)(row >> 3) * 1024u +
            (u32)(row & 7) * 128u + (u32)(k & 63) * 2u;
    return b ^ ((u32)(row & 7) << 4);
}

// ================= Kernel 0: fp32 -> bf16 hi/lo convert (+ zero counters) =================
__global__ void __launch_bounds__(256) conv_kernel(
    const float* __restrict__ x, const float* __restrict__ wa)
{
    if (blockIdx.x == 0 && threadIdx.x < 8) g_ready[threadIdx.x][0] = 0;
    const int XN4 = (BDIM * TSTEPS * HDIM) / 4, WN4 = (HDIM * HDIM) / 4;
    for (int i = blockIdx.x * blockDim.x + threadIdx.x; i < XN4 + WN4;
         i += gridDim.x * blockDim.x) {
        float4 v = (i < XN4) ? ((const float4*)x)[i] : ((const float4*)wa)[i - XN4];
        float f[4] = {v.x, v.y, v.z, v.w};
        unsigned short h[4], l[4];
#pragma unroll
        for (int j = 0; j < 4; j++) { h[j] = f2bf(f[j]); l[j] = f2bf(f[j] - bf2f(h[j])); }
        uint2 ph = make_uint2((u32)h[0] | ((u32)h[1] << 16), (u32)h[2] | ((u32)h[3] << 16));
        uint2 pl = make_uint2((u32)l[0] | ((u32)l[1] << 16), (u32)l[2] | ((u32)l[3] << 16));
        if (i < XN4) { ((uint2*)g_xh)[i] = ph; ((uint2*)g_xl)[i] = pl; }
        else         { ((uint2*)g_wh)[i - XN4] = ph; ((uint2*)g_wl)[i - XN4] = pl; }
    }
}

// ================= Kernel 1: A = x @ Wa^T + ba via mma.sync (unchanged) =================
__global__ void __launch_bounds__(256, 2) xa_mma_kernel(const float* __restrict__ ba)
{
    extern __shared__ char xsm[];
    u32 base = (smem_u32(xsm) + 1023u) & ~1023u;
    const int tid = threadIdx.x, wid = tid >> 5, lan = tid & 31;
    const int nb64 = blockIdx.x * 64, mb = blockIdx.y;

    int srcA[4]; u32 dstA[4];
#pragma unroll
    for (int j = 0; j < 4; j++) {
        int e = tid + j * 256, row = e >> 3, k8 = (e & 7) * 8;
        srcA[j] = (mb * 128 + row) * HDIM + k8;
        dstA[j] = swz64(row, k8);
    }
    int srcB[2]; u32 dstB[2];
#pragma unroll
    for (int j = 0; j < 2; j++) {
        int e = tid + j * 256, row = e >> 3, k8 = (e & 7) * 8;
        srcB[j] = (nb64 + row) * HDIM + k8;
        dstB[j] = swz64(row, k8);
    }
    const int arow = wid * 16 + (lan & 15), acb = (lan >> 4) * 8;
    u32 aoff[4];
#pragma unroll
    for (int k16 = 0; k16 < 4; k16++) aoff[k16] = swz64(arow, k16 * 16 + acb);
    const int grp = lan >> 3;
    u32 boff[4][4];
#pragma unroll
    for (int jp = 0; jp < 4; jp++) {
        int nrow = (2 * jp + (grp >> 1)) * 8 + (lan & 7);
        int kc8 = (grp & 1) * 8;
#pragma unroll
        for (int k16 = 0; k16 < 4; k16++) boff[jp][k16] = swz64(nrow, k16 * 16 + kc8);
    }

    float c[32];
#pragma unroll
    for (int i = 0; i < 32; i++) c[i] = 0.0f;

#define XA_STAGE(bb, so) do {                                             \
    _Pragma("unroll")                                                     \
    for (int j = 0; j < 4; j++) {                                         \
        cpa16((bb) + dstA[j], g_xh + srcA[j] + (so));                     \
        cpa16((bb) + XA_ALO + dstA[j], g_xl + srcA[j] + (so));            \
    }                                                                     \
    _Pragma("unroll")                                                     \
    for (int j = 0; j < 2; j++) {                                         \
        cpa16((bb) + XA_BHI + dstB[j], g_wh + srcB[j] + (so));            \
        cpa16((bb) + XA_BLO + dstB[j], g_wl + srcB[j] + (so));            \
    }                                                                     \
    CP_COMMIT(); } while (0)

    XA_STAGE(base, 0);
    for (int kc = 0; kc < 16; kc++) {
        if (kc < 15) { XA_STAGE(base + ((kc + 1) & 1) * XA_BUF, (kc + 1) * 64); CP_WAIT1(); }
        else         { CP_WAIT0(); }
        __syncthreads();
        const u32 ah = base + (kc & 1) * XA_BUF;
        const u32 al = ah + XA_ALO, bh = ah + XA_BHI, bl = ah + XA_BLO;
#pragma unroll
        for (int k16 = 0; k16 < 4; k16++) {
            u32 a0, a1, a2, a3, l0, l1, l2, l3;
            ldsm_x4(ah + aoff[k16], a0, a1, a2, a3);
            ldsm_x4(al + aoff[k16], l0, l1, l2, l3);
#pragma unroll
            for (int jp = 0; jp < 4; jp++) {
                u32 h0, h1, h2, h3, q0, q1, q2, q3;
                ldsm_x4(bh + boff[jp][k16], h0, h1, h2, h3);
                ldsm_x4(bl + boff[jp][k16], q0, q1, q2, q3);
                float* c0 = c + (2 * jp) * 4;
                float* c1 = c + (2 * jp + 1) * 4;
                mma_bf16(c0, a0, a1, a2, a3, h0, h1);
                mma_bf16(c0, a0, a1, a2, a3, q0, q1);
                mma_bf16(c0, l0, l1, l2, l3, h0, h1);
                mma_bf16(c1, a0, a1, a2, a3, h2, h3);
                mma_bf16(c1, a0, a1, a2, a3, q2, q3);
                mma_bf16(c1, l0, l1, l2, l3, h2, h3);
            }
        }
        __syncthreads();
    }
#pragma unroll
    for (int nt = 0; nt < 8; nt++) {
        int col = nb64 + nt * 8 + (lan & 3) * 2;
        float2 bav = *(const float2*)(ba + col);
        int r0 = mb * 128 + wid * 16 + (lan >> 2);
        *(float2*)&g_A[((size_t)(r0 & 511) * BDIM + (r0 >> 9)) * HDIM + col] =
            make_float2(c[nt * 4 + 0] + bav.x, c[nt * 4 + 1] + bav.y);
        int r1 = r0 + 8;
        *(float2*)&g_A[((size_t)(r1 & 511) * BDIM + (r1 >> 9)) * HDIM + col] =
            make_float2(c[nt * 4 + 2] + bav.x, c[nt * 4 + 3] + bav.y);
    }
}

// ================= Kernel 2: persistent recurrence — warp-per-chunk =================
// Consumer warp w (0-7) owns chunk w each step, all 4 m-tiles; B-hi frags live in
// registers for all 512 steps. Producers = warps 8-11.
// Barriers: FULL per chunk ids 2..9 (cnt 160 = 128 prod + 32 warp); FREE per slot
// ids 10..12 (cnt 160); consumer-internal id 13 (cnt 256).
__global__ void __launch_bounds__(RTHREADS, 1) recur_mma_kernel(
    const float* __restrict__ Wmu,  const float* __restrict__ bmu,
    const float* __restrict__ Wgmu, const float* __restrict__ bgmu,
    const float* __restrict__ Wga,  const float* __restrict__ bga,
    float* __restrict__ out)
{
    extern __shared__ char smem_raw[];
    u32 raw_base = smem_u32(smem_raw);
    u32 abase = (raw_base + 1023u) & ~1023u;
    char* sm = smem_raw + (abase - raw_base);

    const int tid = threadIdx.x, wid = tid >> 5, lan = tid & 31;
    const int cta = blockIdx.x, nb = cta * NB;

    // ---- stage weights into smem (hi/lo, SW128) ----
    for (int u = tid; u < 24 * 128; u += RTHREADS) {
        int r = u >> 7, k = (u & 127) * 8;
        int g = r >> 3, nl = r & 7;
        const float* wp = (g == 0 ? Wmu : (g == 1 ? Wgmu : Wga)) + (size_t)(nb + nl) * HDIM + k;
        float4 v0 = *(const float4*)wp;
        float4 v1 = *(const float4*)(wp + 4);
        float vv[8] = {v0.x, v0.y, v0.z, v0.w, v1.x, v1.y, v1.z, v1.w};
        u32 hw[4], lw[4];
#pragma unroll
        for (int i = 0; i < 4; i++) {
            unsigned short h0 = f2bf(vv[2*i]),   h1 = f2bf(vv[2*i+1]);
            unsigned short l0 = f2bf(vv[2*i]   - bf2f(h0));
            unsigned short l1 = f2bf(vv[2*i+1] - bf2f(h1));
            hw[i] = (u32)h0 | ((u32)h1 << 16);
            lw[i] = (u32)l0 | ((u32)l1 << 16);
        }
        u32 byte = (u32)(k >> 6) * 3072u + (u32)g * 1024u + (u32)(r & 7) * 128u + (u32)(k & 63) * 2u;
        u32 sw = byte ^ ((u32)(r & 7) << 4);
        *(uint4*)(sm + OFF_WHI + sw) = make_uint4(hw[0], hw[1], hw[2], hw[3]);
        *(uint4*)(sm + OFF_WLO + sw) = make_uint4(lw[0], lw[1], lw[2], lw[3]);
    }
    if (tid < 64) {   // h0 = 0
        uint4 z = make_uint4(0, 0, 0, 0);
        *(uint4*)&g_hh[0][tid * HDIM + nb] = z;
        *(uint4*)&g_hl[0][tid * HDIM + nb] = z;
    }
    __syncthreads();
    if (tid == 0) { __threadfence(); red_rel(&g_ready[cta >> 4][0]); }   // h0 produced

    const u32 hsb = abase + OFF_RING, whib = abase + OFF_WHI, wlob = abase + OFF_WLO;

    if (wid >= 8) {
        // ================== PRODUCER (4 warps, 128 threads) ==================
        const int ptid = tid - 256;
        int srcOff[8]; u32 dstOff[8];
#pragma unroll
        for (int j = 0; j < 8; j++) {
            int e = ptid + j * 128, row = e >> 4, k = (e & 15) * 8;
            srcOff[j] = row * HDIM + k;
            dstOff[j] = swzA(row, k);
        }
#define ISSUE_CHUNK(hhp, hlp, sb, so) do {                                  \
    _Pragma("unroll")                                                       \
    for (int j = 0; j < 8; j++) {                                           \
        cpa16((sb) + dstOff[j], (hhp) + srcOff[j] + (so));                  \
        cpa16((sb) + 16384 + dstOff[j], (hlp) + srcOff[j] + (so));          \
    }                                                                       \
    CP_COMMIT(); } while (0)

        wait_cnt_w(0, 16u, lan);
        ISSUE_CHUNK(g_hh[0], g_hl[0], hsb, 0);
        wait_cnt_w(1, 16u, lan);
        ISSUE_CHUNK(g_hh[0], g_hl[0], hsb + SLOT_SZ, KCH);

        int sig = 0;
        for (int m = 2; m <= NTOT; m++) {
            if ((m & 7) == 0 || m == NTOT) {
                CP_WAIT0();                     // drain fully, signal all before blocking
                while (sig < m) { bar_arrive_id(2 + (sig & 7), 160); sig++; }
            } else {
                CP_WAIT1();
                if (sig < m - 1) { bar_arrive_id(2 + (sig & 7), 160); sig++; }
            }
            if (m == NTOT) break;
            if (m >= 3) bar_sync_id(10 + (m % 3), 160);   // slot freed by its consumer warp
            int tm = m >> 3, cm = m & 7;
            wait_cnt_w(cm, 16u * (u32)(tm + 1), lan);
            ISSUE_CHUNK(g_hh[tm & 1], g_hl[tm & 1], hsb + (u32)(m % 3) * SLOT_SZ, cm * KCH);
        }
    } else {
        // ================== CONSUMER (8 warps; warp w owns chunk w) ==================
        const int w = wid;
        const int l15 = lan & 15, aklp = (lan >> 4) * 8;
        const int b7 = lan & 7, bklp = ((lan >> 3) & 1) * 8;
        const u32 wchk = (u32)w * 6144u;                 // this warp's weight k-offset

        // B inner offsets (per kl), shared by hi preload and lo reload
        u32 b_inn[8];
#pragma unroll
        for (int kl = 0; kl < 8; kl++) {
            int bc = kl * 16 + bklp;
            b_inn[kl] = ((u32)(bc >> 6) * 3072u + (u32)b7 * 128u + (u32)(bc & 63) * 2u)
                        ^ ((u32)b7 << 4);
        }
        // preload B-hi fragments for chunk w: resident in registers all 512 steps
        u32 bhi[8][3][2];
#pragma unroll
        for (int kl = 0; kl < 8; kl++)
#pragma unroll
            for (int g = 0; g < 3; g++)
                ldsm_x2(whib + wchk + (u32)g * 1024u + b_inn[kl],
                        bhi[kl][g][0], bhi[kl][g][1]);

        float* ds = (float*)(sm + OFF_D);
        float cb_mu[8], cb_gm[8], cb_ga[8];
#pragma unroll
        for (int i = 0; i < 8; i++) {
            cb_mu[i] = bmu[nb + i]; cb_gm[i] = bgmu[nb + i]; cb_ga[i] = bga[nb + i];
        }

        for (int t = 0; t < TSTEPS; t++) {
            float4 ga0, ga1;
            if (tid < 64) {                               // epilogue data (independent)
                const float* ap = g_A + ((size_t)t * BDIM + tid) * HDIM + nb;
                ga0 = __ldcg((const float4*)ap);
                ga1 = __ldcg((const float4*)(ap + 4));
            }
            float c[48];
#pragma unroll
            for (int i = 0; i < 48; i++) c[i] = 0.0f;

            const int sl = (2 * t + w) % 3;
            bar_sync_id(2 + w, 160);                      // FULL: chunk w staged
            const u32 ahb = hsb + (u32)sl * SLOT_SZ, alb = ahb + 16384;
#pragma unroll
            for (int kl = 0; kl < 8; kl++) {
                u32 blo[3][2];
#pragma unroll
                for (int g = 0; g < 3; g++)
                    ldsm_x2(wlob + wchk + (u32)g * 1024u + b_inn[kl], blo[g][0], blo[g][1]);
#pragma unroll
                for (int mt = 0; mt < 4; mt++) {
                    u32 ao = swzA(mt * 16 + l15, kl * 16 + aklp);
                    u32 ah0, ah1, ah2, ah3, al0, al1, al2, al3;
                    ldsm_x4(ahb + ao, ah0, ah1, ah2, ah3);
                    ldsm_x4(alb + ao, al0, al1, al2, al3);
#pragma unroll
                    for (int g = 0; g < 3; g++) {
                        float* cc = c + (mt * 3 + g) * 4;
                        mma_bf16(cc, ah0, ah1, ah2, ah3, bhi[kl][g][0], bhi[kl][g][1]);
                        mma_bf16(cc, ah0, ah1, ah2, ah3, blo[g][0], blo[g][1]);
                        mma_bf16(cc, al0, al1, al2, al3, bhi[kl][g][0], bhi[kl][g][1]);
                    }
                }
            }
            bar_arrive_id(10 + sl, 160);                  // FREE slot

            // ---- 2-stage partial-D reduction over the 8 k-chunks ----
            const int rr = lan >> 2, cc2 = (lan & 3) * 2;
            if (w < 4) {
                float* dsw = ds + w * DSZ;
#pragma unroll
                for (int mt = 0; mt < 4; mt++)
#pragma unroll
                    for (int g = 0; g < 3; g++) {
                        const float* cf = c + (mt * 3 + g) * 4;
                        *(float2*)&dsw[(mt*16+rr)   * DS_STRIDE + g*8 + cc2] = make_float2(cf[0], cf[1]);
                        *(float2*)&dsw[(mt*16+rr+8) * DS_STRIDE + g*8 + cc2] = make_float2(cf[2], cf[3]);
                    }
            }
            bar_sync_id(13, 256);
            if (w >= 4) {
                float* dsw = ds + (w - 4) * DSZ;
#pragma unroll
                for (int mt = 0; mt < 4; mt++)
#pragma unroll
                    for (int g = 0; g < 3; g++) {
                        const float* cf = c + (mt * 3 + g) * 4;
                        float2* p0 = (float2*)&dsw[(mt*16+rr)   * DS_STRIDE + g*8 + cc2];
                        float2* p1 = (float2*)&dsw[(mt*16+rr+8) * DS_STRIDE + g*8 + cc2];
                        float2 v0 = *p0, v1 = *p1;
                        *p0 = make_float2(v0.x + cf[0], v0.y + cf[1]);
                        *p1 = make_float2(v1.x + cf[2], v1.y + cf[3]);
                    }
            }
            bar_sync_id(13, 256);
            if (tid < 64) {
                float dsum[24];
#pragma unroll
                for (int i = 0; i < 24; i += 2) {      // float2: ds rows are 8B-aligned (26*4=104)
                    float2 s = *(const float2*)&ds[tid * DS_STRIDE + i];
#pragma unroll
                    for (int b = 1; b < 4; b++) {
                        float2 v = *(const float2*)&ds[b * DSZ + tid * DS_STRIDE + i];
                        s.x += v.x; s.y += v.y;
                    }
                    dsum[i] = s.x; dsum[i + 1] = s.y;
                }
                float av[8] = {ga0.x, ga0.y, ga0.z, ga0.w, ga1.x, ga1.y, ga1.z, ga1.w};
                float ov[8];
#pragma unroll
                for (int i = 0; i < 8; i++) {
                    float mu = dsum[i] + cb_mu[i];
                    float gm = dsum[8 + i] + cb_gm[i];
                    float ga = dsum[16 + i] + cb_ga[i];
                    ov[i] = mu * sigf(gm) + av[i] * sigf(ga);
                }
                u32 hw[4], lw[4];
#pragma unroll
                for (int i = 0; i < 4; i++) {
                    unsigned short h0 = f2bf(ov[2*i]),   h1 = f2bf(ov[2*i+1]);
                    unsigned short l0 = f2bf(ov[2*i]   - bf2f(h0));
                    unsigned short l1 = f2bf(ov[2*i+1] - bf2f(h1));
                    hw[i] = (u32)h0 | ((u32)h1 << 16);
                    lw[i] = (u32)l0 | ((u32)l1 << 16);
                }
                __stcg((uint4*)&g_hh[(t + 1) & 1][tid * HDIM + nb], make_uint4(hw[0], hw[1], hw[2], hw[3]));
                __stcg((uint4*)&g_hl[(t + 1) & 1][tid * HDIM + nb], make_uint4(lw[0], lw[1], lw[2], lw[3]));
                if (t == TSTEPS - 1) {
                    *(float4*)(out + (size_t)tid * HDIM + nb)     = make_float4(ov[0], ov[1], ov[2], ov[3]);
                    *(float4*)(out + (size_t)tid * HDIM + nb + 4) = make_float4(ov[4], ov[5], ov[6], ov[7]);
                }
            }
            bar_sync_id(13, 256);
            if (tid == 0) { __threadfence(); red_rel(&g_ready[cta >> 4][0]); }
        }
    }
}

// ================= launch =================
extern "C" void kernel_launch(void* const* d_in, const int* in_sizes, int n_in,
                              void* d_out, int out_size) {
    const float* x    = (const float*)d_in[0];
    const float* Wmu  = (const float*)d_in[1];
    const float* bmu  = (const float*)d_in[2];
    const float* Wgmu = (const float*)d_in[3];
    const float* bgmu = (const float*)d_in[4];
    const float* Wa   = (const float*)d_in[5];
    const float* ba   = (const float*)d_in[6];
    const float* Wga  = (const float*)d_in[7];
    const float* bga  = (const float*)d_in[8];
    float* out = (float*)d_out;

    conv_kernel<<<2048, 256>>>(x, Wa);

    cudaFuncSetAttribute(xa_mma_kernel, cudaFuncAttributeMaxDynamicSharedMemorySize, XA_SMEM);
    xa_mma_kernel<<<dim3(16, 256), 256, XA_SMEM>>>(ba);

    cudaFuncSetAttribute(recur_mma_kernel, cudaFuncAttributeMaxDynamicSharedMemorySize, SMEM_TOTAL);
    recur_mma_kernel<<<NCTA, RTHREADS, SMEM_TOTAL>>>(Wmu, bmu, Wgmu, bgmu, Wga, bga, out);
}

// round 16
// speedup vs baseline: 1.5516x; 1.5516x over previous
#include <cuda_runtime.h>
#include <cuda_bf16.h>
#include <cstdint>

typedef unsigned long long ull;
typedef unsigned int u32;

#define HDIM 1024
#define BDIM 64
#define TSTEPS 512
#define NCTA 128
#define NB 8
#define RTHREADS 256
#define KCH 128
#define NCHUNK 8
#define NTOT (TSTEPS * NCHUNK)

// recur smem (relative to 1024B-aligned base)
#define OFF_WHI 0
#define OFF_WLO 49152
#define OFF_RING 98304             // 3 slots x 32768 (hi 16K + lo 16K)
#define SLOT_SZ 32768
#define OFF_D   196608
#define SMEM_USED 203264
#define SMEM_TOTAL (SMEM_USED + 1024)
#define DS_STRIDE 26

// xa smem per buffer: Ahi 16K | Alo 16K | Bhi 8K | Blo 8K
#define XA_ALO 16384
#define XA_BHI 32768
#define XA_BLO 40960
#define XA_BUF 49152
#define XA_SMEM (2 * XA_BUF + 1024)

__device__ float g_A[(size_t)TSTEPS * BDIM * HDIM];          // [T][B][H]
__device__ __nv_bfloat16 g_xh[(size_t)BDIM * TSTEPS * HDIM];
__device__ __nv_bfloat16 g_xl[(size_t)BDIM * TSTEPS * HDIM];
__device__ __nv_bfloat16 g_wh[HDIM * HDIM];
__device__ __nv_bfloat16 g_wl[HDIM * HDIM];
__device__ __nv_bfloat16 g_hh[2][BDIM * HDIM];
__device__ __nv_bfloat16 g_hl[2][BDIM * HDIM];
__device__ u32 g_ready[8][32];                               // one 128B line per counter

// ---------------- helpers ----------------
__device__ __forceinline__ u32 smem_u32(const void* p) {
    u32 a;
    asm("{ .reg .u64 t; cvta.to.shared.u64 t, %1; cvt.u32.u64 %0, t; }" : "=r"(a) : "l"(p));
    return a;
}
__device__ __forceinline__ void ldsm_x4(u32 a, u32& r0, u32& r1, u32& r2, u32& r3) {
    asm volatile("ldmatrix.sync.aligned.m8n8.x4.shared.b16 {%0,%1,%2,%3}, [%4];"
                 : "=r"(r0), "=r"(r1), "=r"(r2), "=r"(r3) : "r"(a));
}
__device__ __forceinline__ void mma_bf16(float* c, u32 a0, u32 a1, u32 a2, u32 a3, u32 b0, u32 b1) {
    asm volatile(
        "mma.sync.aligned.m16n8k16.row.col.f32.bf16.bf16.f32 "
        "{%0,%1,%2,%3}, {%4,%5,%6,%7}, {%8,%9}, {%0,%1,%2,%3};"
        : "+f"(c[0]), "+f"(c[1]), "+f"(c[2]), "+f"(c[3])
        : "r"(a0), "r"(a1), "r"(a2), "r"(a3), "r"(b0), "r"(b1));
}
__device__ __forceinline__ void cpa16(u32 d, const void* s) {
    asm volatile("cp.async.cg.shared.global [%0], [%1], 16;" :: "r"(d), "l"(s) : "memory");
}
#define CP_COMMIT() asm volatile("cp.async.commit_group;" ::: "memory")
#define CP_WAIT0()  asm volatile("cp.async.wait_group 0;" ::: "memory")
#define CP_WAIT1()  asm volatile("cp.async.wait_group 1;" ::: "memory")
__device__ __forceinline__ void bar_sync_id(int id, int cnt) {
    asm volatile("bar.sync %0, %1;" :: "r"(id), "r"(cnt) : "memory");
}
__device__ __forceinline__ void bar_arrive_id(int id, int cnt) {
    asm volatile("bar.arrive %0, %1;" :: "r"(id), "r"(cnt) : "memory");
}
__device__ __forceinline__ unsigned short f2bf(float f) { return __bfloat16_as_ushort(__float2bfloat16(f)); }
__device__ __forceinline__ float bf2f(unsigned short s) { return __bfloat162float(__ushort_as_bfloat16(s)); }
__device__ __forceinline__ float sigf(float x) { return 1.0f / (1.0f + __expf(-x)); }
__device__ __forceinline__ u32 ld_acq(const u32* p) {
    u32 v;
    asm volatile("ld.acquire.gpu.global.u32 %0, [%1];" : "=r"(v) : "l"(p) : "memory");
    return v;
}
__device__ __forceinline__ void red_rel(u32* p) {
    asm volatile("red.release.gpu.global.add.u32 [%0], %1;" :: "l"(p), "r"(1u) : "memory");
}
__device__ __forceinline__ void wait_cnt_w(int c, u32 need, int lane) {
    if (lane == 0) {
        const u32* p = &g_ready[c][0];
        while (ld_acq(p) < need) { __nanosleep(40); }
    }
    __syncwarp();
}
__device__ __forceinline__ u32 swz64(int row, int k) {   // 64-col bf16 tile, 128B rows
    u32 b = (u32)(row >> 3) * 1024u + (u32)(row & 7) * 128u + (u32)(k & 63) * 2u;
    return b ^ ((u32)(row & 7) << 4);
}
__device__ __forceinline__ u32 swzA(int row, int k) {    // A tile [64 rows][128 k]
    u32 b = (u32)(k >> 6) * 8192u + (u32)(row >> 3) * 1024u +
            (u32)(row & 7) * 128u + (u32)(k & 63) * 2u;
    return b ^ ((u32)(row & 7) << 4);
}

// ================= Kernel 0: fp32 -> bf16 hi/lo convert (+ zero counters) =================
__global__ void __launch_bounds__(256) conv_kernel(
    const float* __restrict__ x, const float* __restrict__ wa)
{
    if (blockIdx.x == 0 && threadIdx.x < 8) g_ready[threadIdx.x][0] = 0;
    const int XN4 = (BDIM * TSTEPS * HDIM) / 4, WN4 = (HDIM * HDIM) / 4;
    for (int i = blockIdx.x * blockDim.x + threadIdx.x; i < XN4 + WN4;
         i += gridDim.x * blockDim.x) {
        float4 v = (i < XN4) ? ((const float4*)x)[i] : ((const float4*)wa)[i - XN4];
        float f[4] = {v.x, v.y, v.z, v.w};
        unsigned short h[4], l[4];
#pragma unroll
        for (int j = 0; j < 4; j++) { h[j] = f2bf(f[j]); l[j] = f2bf(f[j] - bf2f(h[j])); }
        uint2 ph = make_uint2((u32)h[0] | ((u32)h[1] << 16), (u32)h[2] | ((u32)h[3] << 16));
        uint2 pl = make_uint2((u32)l[0] | ((u32)l[1] << 16), (u32)l[2] | ((u32)l[3] << 16));
        if (i < XN4) { ((uint2*)g_xh)[i] = ph; ((uint2*)g_xl)[i] = pl; }
        else         { ((uint2*)g_wh)[i - XN4] = ph; ((uint2*)g_wl)[i - XN4] = pl; }
    }
}

// ================= Kernel 1: A = x @ Wa^T + ba via mma.sync (unchanged) =================
__global__ void __launch_bounds__(256, 2) xa_mma_kernel(const float* __restrict__ ba)
{
    extern __shared__ char xsm[];
    u32 base = (smem_u32(xsm) + 1023u) & ~1023u;
    const int tid = threadIdx.x, wid = tid >> 5, lan = tid & 31;
    const int nb64 = blockIdx.x * 64, mb = blockIdx.y;

    int srcA[4]; u32 dstA[4];
#pragma unroll
    for (int j = 0; j < 4; j++) {
        int e = tid + j * 256, row = e >> 3, k8 = (e & 7) * 8;
        srcA[j] = (mb * 128 + row) * HDIM + k8;
        dstA[j] = swz64(row, k8);
    }
    int srcB[2]; u32 dstB[2];
#pragma unroll
    for (int j = 0; j < 2; j++) {
        int e = tid + j * 256, row = e >> 3, k8 = (e & 7) * 8;
        srcB[j] = (nb64 + row) * HDIM + k8;
        dstB[j] = swz64(row, k8);
    }
    const int arow = wid * 16 + (lan & 15), acb = (lan >> 4) * 8;
    u32 aoff[4];
#pragma unroll
    for (int k16 = 0; k16 < 4; k16++) aoff[k16] = swz64(arow, k16 * 16 + acb);
    const int grp = lan >> 3;
    u32 boff[4][4];
#pragma unroll
    for (int jp = 0; jp < 4; jp++) {
        int nrow = (2 * jp + (grp >> 1)) * 8 + (lan & 7);
        int kc8 = (grp & 1) * 8;
#pragma unroll
        for (int k16 = 0; k16 < 4; k16++) boff[jp][k16] = swz64(nrow, k16 * 16 + kc8);
    }

    float c[32];
#pragma unroll
    for (int i = 0; i < 32; i++) c[i] = 0.0f;

#define XA_STAGE(bb, so) do {                                             \
    _Pragma("unroll")                                                     \
    for (int j = 0; j < 4; j++) {                                         \
        cpa16((bb) + dstA[j], g_xh + srcA[j] + (so));                     \
        cpa16((bb) + XA_ALO + dstA[j], g_xl + srcA[j] + (so));            \
    }                                                                     \
    _Pragma("unroll")                                                     \
    for (int j = 0; j < 2; j++) {                                         \
        cpa16((bb) + XA_BHI + dstB[j], g_wh + srcB[j] + (so));            \
        cpa16((bb) + XA_BLO + dstB[j], g_wl + srcB[j] + (so));            \
    }                                                                     \
    CP_COMMIT(); } while (0)

    XA_STAGE(base, 0);
    for (int kc = 0; kc < 16; kc++) {
        if (kc < 15) { XA_STAGE(base + ((kc + 1) & 1) * XA_BUF, (kc + 1) * 64); CP_WAIT1(); }
        else         { CP_WAIT0(); }
        __syncthreads();
        const u32 ah = base + (kc & 1) * XA_BUF;
        const u32 al = ah + XA_ALO, bh = ah + XA_BHI, bl = ah + XA_BLO;
#pragma unroll
        for (int k16 = 0; k16 < 4; k16++) {
            u32 a0, a1, a2, a3, l0, l1, l2, l3;
            ldsm_x4(ah + aoff[k16], a0, a1, a2, a3);
            ldsm_x4(al + aoff[k16], l0, l1, l2, l3);
#pragma unroll
            for (int jp = 0; jp < 4; jp++) {
                u32 h0, h1, h2, h3, q0, q1, q2, q3;
                ldsm_x4(bh + boff[jp][k16], h0, h1, h2, h3);
                ldsm_x4(bl + boff[jp][k16], q0, q1, q2, q3);
                float* c0 = c + (2 * jp) * 4;
                float* c1 = c + (2 * jp + 1) * 4;
                mma_bf16(c0, a0, a1, a2, a3, h0, h1);
                mma_bf16(c0, a0, a1, a2, a3, q0, q1);
                mma_bf16(c0, l0, l1, l2, l3, h0, h1);
                mma_bf16(c1, a0, a1, a2, a3, h2, h3);
                mma_bf16(c1, a0, a1, a2, a3, q2, q3);
                mma_bf16(c1, l0, l1, l2, l3, h2, h3);
            }
        }
        __syncthreads();
    }
#pragma unroll
    for (int nt = 0; nt < 8; nt++) {
        int col = nb64 + nt * 8 + (lan & 3) * 2;
        float2 bav = *(const float2*)(ba + col);
        int r0 = mb * 128 + wid * 16 + (lan >> 2);
        *(float2*)&g_A[((size_t)(r0 & 511) * BDIM + (r0 >> 9)) * HDIM + col] =
            make_float2(c[nt * 4 + 0] + bav.x, c[nt * 4 + 1] + bav.y);
        int r1 = r0 + 8;
        *(float2*)&g_A[((size_t)(r1 & 511) * BDIM + (r1 >> 9)) * HDIM + col] =
            make_float2(c[nt * 4 + 2] + bav.x, c[nt * 4 + 3] + bav.y);
    }
}

// ================= Kernel 2: persistent recurrence (r9 skeleton) =================
// Warps 0-3 consumers (one m-tile each, sweep all 8 chunks), warps 4-7 producers.
// FULL barriers ids 2..4 (producer arrive, consumer sync); FREE ids 5..7 (reverse).
__global__ void __launch_bounds__(RTHREADS, 1) recur_mma_kernel(
    const float* __restrict__ Wmu,  const float* __restrict__ bmu,
    const float* __restrict__ Wgmu, const float* __restrict__ bgmu,
    const float* __restrict__ Wga,  const float* __restrict__ bga,
    float* __restrict__ out)
{
    extern __shared__ char smem_raw[];
    u32 raw_base = smem_u32(smem_raw);
    u32 abase = (raw_base + 1023u) & ~1023u;
    char* sm = smem_raw + (abase - raw_base);

    const int tid = threadIdx.x, wid = tid >> 5, lan = tid & 31;
    const int cta = blockIdx.x, nb = cta * NB;

    // ---- stage weights (resident all 512 steps) ----
    for (int u = tid; u < 24 * 128; u += RTHREADS) {
        int r = u >> 7, k = (u & 127) * 8;
        int g = r >> 3, nl = r & 7;
        const float* wp = (g == 0 ? Wmu : (g == 1 ? Wgmu : Wga)) + (size_t)(nb + nl) * HDIM + k;
        float4 v0 = *(const float4*)wp;
        float4 v1 = *(const float4*)(wp + 4);
        float vv[8] = {v0.x, v0.y, v0.z, v0.w, v1.x, v1.y, v1.z, v1.w};
        u32 hw[4], lw[4];
#pragma unroll
        for (int i = 0; i < 4; i++) {
            unsigned short h0 = f2bf(vv[2*i]),   h1 = f2bf(vv[2*i+1]);
            unsigned short l0 = f2bf(vv[2*i]   - bf2f(h0));
            unsigned short l1 = f2bf(vv[2*i+1] - bf2f(h1));
            hw[i] = (u32)h0 | ((u32)h1 << 16);
            lw[i] = (u32)l0 | ((u32)l1 << 16);
        }
        u32 byte = (u32)(k >> 6) * 3072u + (u32)g * 1024u + (u32)(r & 7) * 128u + (u32)(k & 63) * 2u;
        u32 sw = byte ^ ((u32)(r & 7) << 4);
        *(uint4*)(sm + OFF_WHI + sw) = make_uint4(hw[0], hw[1], hw[2], hw[3]);
        *(uint4*)(sm + OFF_WLO + sw) = make_uint4(lw[0], lw[1], lw[2], lw[3]);
    }
    if (tid < 64) {   // h0 = 0
        uint4 z = make_uint4(0, 0, 0, 0);
        *(uint4*)&g_hh[0][tid * HDIM + nb] = z;
        *(uint4*)&g_hl[0][tid * HDIM + nb] = z;
    }
    __syncthreads();
    if (tid == 0) red_rel(&g_ready[cta >> 4][0]);   // h0 produced

    const u32 hsb = abase + OFF_RING, whib = abase + OFF_WHI, wlob = abase + OFF_WLO;

    if (wid >= 4) {
        // ================== PRODUCER (identical to r9) ==================
        const int ptid = tid & 127;
        int srcOff[8]; u32 dstOff[8];
#pragma unroll
        for (int j = 0; j < 8; j++) {
            int e = ptid + j * 128, row = e >> 4, k = (e & 15) * 8;
            srcOff[j] = row * HDIM + k;
            dstOff[j] = swzA(row, k);
        }
#define ISSUE_CHUNK(hhp, hlp, sb, so) do {                                  \
    _Pragma("unroll")                                                       \
    for (int j = 0; j < 8; j++) {                                           \
        cpa16((sb) + dstOff[j], (hhp) + srcOff[j] + (so));                  \
        cpa16((sb) + 16384 + dstOff[j], (hlp) + srcOff[j] + (so));          \
    }                                                                       \
    CP_COMMIT(); } while (0)

        wait_cnt_w(0, 16u, lan);
        ISSUE_CHUNK(g_hh[0], g_hl[0], hsb, 0);
        wait_cnt_w(1, 16u, lan);
        ISSUE_CHUNK(g_hh[0], g_hl[0], hsb + SLOT_SZ, KCH);

        int sig = 0, sig_sl = 0, m_sl = 2;
        for (int m = 2; m <= NTOT; m++) {
            if ((m & 7) == 0 || m == NTOT) {
                CP_WAIT0();                     // drain fully, signal all before blocking
                while (sig < m) {
                    bar_arrive_id(2 + sig_sl, 256);
                    sig++; if (++sig_sl == 3) sig_sl = 0;
                }
            } else {
                CP_WAIT1();
                if (sig < m - 1) {
                    bar_arrive_id(2 + sig_sl, 256);
                    sig++; if (++sig_sl == 3) sig_sl = 0;
                }
            }
            if (m == NTOT) break;
            if (m >= 3) bar_sync_id(5 + m_sl, 256);        // consumer freed chunk m-3
            int tm = m >> 3, cm = m & 7;
            wait_cnt_w(cm, 16u * (u32)(tm + 1), lan);
            ISSUE_CHUNK(g_hh[tm & 1], g_hl[tm & 1], hsb + (u32)m_sl * SLOT_SZ, cm * KCH);
            if (++m_sl == 3) m_sl = 0;
        }
    } else {
        // ================== CONSUMER (packed-B + A double-buffer) ==================
        const int mt = wid;
        const int l15 = lan & 15, aklp = (lan >> 4) * 8;
        const int mi = lan >> 3, r7 = lan & 7;
        const u32 bbase = (mi < 2) ? whib : wlob;        // lanes 0-15 Whi, 16-31 Wlo
        u32 a_off[8], b_inn[8];
#pragma unroll
        for (int kl = 0; kl < 8; kl++) {
            a_off[kl] = swzA(mt * 16 + l15, kl * 16 + aklp);
            int bc = kl * 16 + (mi & 1) * 8;
            b_inn[kl] = ((u32)(bc >> 6) * 3072u + (u32)r7 * 128u + (u32)(bc & 63) * 2u)
                        ^ ((u32)r7 << 4);
        }
        float* ds = (float*)(sm + OFF_D);
        float cb_mu[8], cb_gm[8], cb_ga[8];
#pragma unroll
        for (int i = 0; i < 8; i++) {
            cb_mu[i] = bmu[nb + i]; cb_gm[i] = bgmu[nb + i]; cb_ga[i] = bga[nb + i];
        }

        int sl = 0;
        for (int t = 0; t < TSTEPS; t++) {
            float c[12];
#pragma unroll
            for (int i = 0; i < 12; i++) c[i] = 0.0f;
            float4 ga0 = make_float4(0, 0, 0, 0), ga1 = ga0;

            for (int kc = 0; kc < NCHUNK; kc++) {
                bar_sync_id(2 + sl, 256);                   // slot full
                if (kc == 6 && tid < 64) {
                    const float* ap = g_A + ((size_t)t * BDIM + tid) * HDIM + nb;
                    ga0 = __ldcg((const float4*)ap);
                    ga1 = __ldcg((const float4*)(ap + 4));
                }
                const u32 ahb = hsb + (u32)sl * SLOT_SZ, alb = ahb + 16384;
                const u32 wko = (u32)kc * 6144u;
                u32 Ah[2][4], Al[2][4];
                ldsm_x4(ahb + a_off[0], Ah[0][0], Ah[0][1], Ah[0][2], Ah[0][3]);
                ldsm_x4(alb + a_off[0], Al[0][0], Al[0][1], Al[0][2], Al[0][3]);
#pragma unroll
                for (int kl = 0; kl < 8; kl++) {
                    const int cur = kl & 1, nxt = cur ^ 1;
                    if (kl < 7) {                           // prefetch next A under this kl's MMAs
                        ldsm_x4(ahb + a_off[kl + 1], Ah[nxt][0], Ah[nxt][1], Ah[nxt][2], Ah[nxt][3]);
                        ldsm_x4(alb + a_off[kl + 1], Al[nxt][0], Al[nxt][1], Al[nxt][2], Al[nxt][3]);
                    }
#pragma unroll
                    for (int g = 0; g < 3; g++) {
                        u32 bh0, bh1, bl0, bl1;
                        ldsm_x4(bbase + wko + (u32)g * 1024u + b_inn[kl], bh0, bh1, bl0, bl1);
                        mma_bf16(c + g * 4, Ah[cur][0], Ah[cur][1], Ah[cur][2], Ah[cur][3], bh0, bh1);
                        mma_bf16(c + g * 4, Ah[cur][0], Ah[cur][1], Ah[cur][2], Ah[cur][3], bl0, bl1);
                        mma_bf16(c + g * 4, Al[cur][0], Al[cur][1], Al[cur][2], Al[cur][3], bh0, bh1);
                    }
                }
                bar_arrive_id(5 + sl, 256);                 // slot free
                if (++sl == 3) sl = 0;
            }

            // ---- D exchange + epilogue (identical to r9) ----
            int r0 = mt * 16 + (lan >> 2), cc = (lan & 3) * 2;
#pragma unroll
            for (int g = 0; g < 3; g++) {
                *(float2*)&ds[r0 * DS_STRIDE + g * 8 + cc]       = make_float2(c[g*4+0], c[g*4+1]);
                *(float2*)&ds[(r0 + 8) * DS_STRIDE + g * 8 + cc] = make_float2(c[g*4+2], c[g*4+3]);
            }
            bar_sync_id(1, 128);
            if (tid < 64) {
                const float* drow = ds + tid * DS_STRIDE;
                float av[8] = {ga0.x, ga0.y, ga0.z, ga0.w, ga1.x, ga1.y, ga1.z, ga1.w};
                float ov[8];
#pragma unroll
                for (int i = 0; i < 8; i++) {
                    float mu = drow[i] + cb_mu[i];
                    float gm = drow[8 + i] + cb_gm[i];
                    float ga = drow[16 + i] + cb_ga[i];
                    ov[i] = mu * sigf(gm) + av[i] * sigf(ga);
                }
                u32 hw[4], lw[4];
#pragma unroll
                for (int i = 0; i < 4; i++) {
                    unsigned short h0 = f2bf(ov[2*i]),   h1 = f2bf(ov[2*i+1]);
                    unsigned short l0 = f2bf(ov[2*i]   - bf2f(h0));
                    unsigned short l1 = f2bf(ov[2*i+1] - bf2f(h1));
                    hw[i] = (u32)h0 | ((u32)h1 << 16);
                    lw[i] = (u32)l0 | ((u32)l1 << 16);
                }
                __stcg((uint4*)&g_hh[(t + 1) & 1][tid * HDIM + nb], make_uint4(hw[0], hw[1], hw[2], hw[3]));
                __stcg((uint4*)&g_hl[(t + 1) & 1][tid * HDIM + nb], make_uint4(lw[0], lw[1], lw[2], lw[3]));
                if (t == TSTEPS - 1) {
                    *(float4*)(out + (size_t)tid * HDIM + nb)     = make_float4(ov[0], ov[1], ov[2], ov[3]);
                    *(float4*)(out + (size_t)tid * HDIM + nb + 4) = make_float4(ov[4], ov[5], ov[6], ov[7]);
                }
            }
            bar_sync_id(1, 128);
            if (tid == 0) red_rel(&g_ready[cta >> 4][0]);
        }
    }
}

// ================= launch =================
extern "C" void kernel_launch(void* const* d_in, const int* in_sizes, int n_in,
                              void* d_out, int out_size) {
    const float* x    = (const float*)d_in[0];
    const float* Wmu  = (const float*)d_in[1];
    const float* bmu  = (const float*)d_in[2];
    const float* Wgmu = (const float*)d_in[3];
    const float* bgmu = (const float*)d_in[4];
    const float* Wa   = (const float*)d_in[5];
    const float* ba   = (const float*)d_in[6];
    const float* Wga  = (const float*)d_in[7];
    const float* bga  = (const float*)d_in[8];
    float* out = (float*)d_out;

    conv_kernel<<<2048, 256>>>(x, Wa);

    cudaFuncSetAttribute(xa_mma_kernel, cudaFuncAttributeMaxDynamicSharedMemorySize, XA_SMEM);
    xa_mma_kernel<<<dim3(16, 256), 256, XA_SMEM>>>(ba);

    cudaFuncSetAttribute(recur_mma_kernel, cudaFuncAttributeMaxDynamicSharedMemorySize, SMEM_TOTAL);
    recur_mma_kernel<<<NCTA, RTHREADS, SMEM_TOTAL>>>(Wmu, bmu, Wgmu, bgmu, Wga, bga, out);
}

// round 17
// speedup vs baseline: 1.6389x; 1.0563x over previous
#include <cuda_runtime.h>
#include <cuda_bf16.h>
#include <cstdint>

typedef unsigned long long ull;
typedef unsigned int u32;

#define HDIM 1024
#define BDIM 64
#define TSTEPS 512
#define NCTA 128
#define NB 8
#define RTHREADS 256
#define KCH 128
#define NCHUNK 8
#define NTOT (TSTEPS * NCHUNK)

// recur smem (relative to 1024B-aligned base)
#define OFF_WHI 0
#define OFF_WLO 49152
#define OFF_RING 98304             // 3 slots x 32768 (hi 16K + lo 16K)
#define SLOT_SZ 32768
#define OFF_D   196608             // 2 step-parity buffers x 64x26 floats
#define DS_STRIDE 26
#define DSZ (64 * DS_STRIDE)
#define SMEM_USED (196608 + 2 * DSZ * 4)
#define SMEM_TOTAL (SMEM_USED + 1024)

// xa smem per buffer: Ahi 16K | Alo 16K | Bhi 8K | Blo 8K
#define XA_ALO 16384
#define XA_BHI 32768
#define XA_BLO 40960
#define XA_BUF 49152
#define XA_SMEM (2 * XA_BUF + 1024)

__device__ float g_A[(size_t)TSTEPS * BDIM * HDIM];          // [T][B][H]
__device__ __nv_bfloat16 g_xh[(size_t)BDIM * TSTEPS * HDIM];
__device__ __nv_bfloat16 g_xl[(size_t)BDIM * TSTEPS * HDIM];
__device__ __nv_bfloat16 g_wh[HDIM * HDIM];
__device__ __nv_bfloat16 g_wl[HDIM * HDIM];
__device__ __nv_bfloat16 g_hh[2][BDIM * HDIM];
__device__ __nv_bfloat16 g_hl[2][BDIM * HDIM];
__device__ u32 g_ready[8][32];                               // one 128B line per counter

// ---------------- helpers ----------------
__device__ __forceinline__ u32 smem_u32(const void* p) {
    u32 a;
    asm("{ .reg .u64 t; cvta.to.shared.u64 t, %1; cvt.u32.u64 %0, t; }" : "=r"(a) : "l"(p));
    return a;
}
__device__ __forceinline__ void ldsm_x4(u32 a, u32& r0, u32& r1, u32& r2, u32& r3) {
    asm volatile("ldmatrix.sync.aligned.m8n8.x4.shared.b16 {%0,%1,%2,%3}, [%4];"
                 : "=r"(r0), "=r"(r1), "=r"(r2), "=r"(r3) : "r"(a));
}
__device__ __forceinline__ void mma_bf16(float* c, u32 a0, u32 a1, u32 a2, u32 a3, u32 b0, u32 b1) {
    asm volatile(
        "mma.sync.aligned.m16n8k16.row.col.f32.bf16.bf16.f32 "
        "{%0,%1,%2,%3}, {%4,%5,%6,%7}, {%8,%9}, {%0,%1,%2,%3};"
        : "+f"(c[0]), "+f"(c[1]), "+f"(c[2]), "+f"(c[3])
        : "r"(a0), "r"(a1), "r"(a2), "r"(a3), "r"(b0), "r"(b1));
}
__device__ __forceinline__ void cpa16(u32 d, const void* s) {
    asm volatile("cp.async.cg.shared.global [%0], [%1], 16;" :: "r"(d), "l"(s) : "memory");
}
#define CP_COMMIT() asm volatile("cp.async.commit_group;" ::: "memory")
#define CP_WAIT0()  asm volatile("cp.async.wait_group 0;" ::: "memory")
#define CP_WAIT1()  asm volatile("cp.async.wait_group 1;" ::: "memory")
__device__ __forceinline__ void bar_sync_id(int id, int cnt) {
    asm volatile("bar.sync %0, %1;" :: "r"(id), "r"(cnt) : "memory");
}
__device__ __forceinline__ void bar_arrive_id(int id, int cnt) {
    asm volatile("bar.arrive %0, %1;" :: "r"(id), "r"(cnt) : "memory");
}
__device__ __forceinline__ unsigned short f2bf(float f) { return __bfloat16_as_ushort(__float2bfloat16(f)); }
__device__ __forceinline__ float bf2f(unsigned short s) { return __bfloat162float(__ushort_as_bfloat16(s)); }
__device__ __forceinline__ float sigf(float x) { return 1.0f / (1.0f + __expf(-x)); }
__device__ __forceinline__ u32 ld_acq(const u32* p) {
    u32 v;
    asm volatile("ld.acquire.gpu.global.u32 %0, [%1];" : "=r"(v) : "l"(p) : "memory");
    return v;
}
__device__ __forceinline__ void red_rel(u32* p) {
    asm volatile("red.release.gpu.global.add.u32 [%0], %1;" :: "l"(p), "r"(1u) : "memory");
}
__device__ __forceinline__ void wait_cnt_w(int c, u32 need, int lane) {
    if (lane == 0) {
        const u32* p = &g_ready[c][0];
        while (ld_acq(p) < need) { __nanosleep(20); }
    }
    __syncwarp();
}
__device__ __forceinline__ u32 swz64(int row, int k) {   // 64-col bf16 tile, 128B rows
    u32 b = (u32)(row >> 3) * 1024u + (u32)(row & 7) * 128u + (u32)(k & 63) * 2u;
    return b ^ ((u32)(row & 7) << 4);
}
__device__ __forceinline__ u32 swzA(int row, int k) {    // A tile [64 rows][128 k]
    u32 b = (u32)(k >> 6) * 8192u + (u32)(row >> 3) * 1024u +
            (u32)(row & 7) * 128u + (u32)(k & 63) * 2u;
    return b ^ ((u32)(row & 7) << 4);
}

// ================= Kernel 0: fp32 -> bf16 hi/lo convert (+ zero counters) =================
__global__ void __launch_bounds__(256) conv_kernel(
    const float* __restrict__ x, const float* __restrict__ wa)
{
    if (blockIdx.x == 0 && threadIdx.x < 8) g_ready[threadIdx.x][0] = 0;
    const int XN4 = (BDIM * TSTEPS * HDIM) / 4, WN4 = (HDIM * HDIM) / 4;
    for (int i = blockIdx.x * blockDim.x + threadIdx.x; i < XN4 + WN4;
         i += gridDim.x * blockDim.x) {
        float4 v = (i < XN4) ? ((const float4*)x)[i] : ((const float4*)wa)[i - XN4];
        float f[4] = {v.x, v.y, v.z, v.w};
        unsigned short h[4], l[4];
#pragma unroll
        for (int j = 0; j < 4; j++) { h[j] = f2bf(f[j]); l[j] = f2bf(f[j] - bf2f(h[j])); }
        uint2 ph = make_uint2((u32)h[0] | ((u32)h[1] << 16), (u32)h[2] | ((u32)h[3] << 16));
        uint2 pl = make_uint2((u32)l[0] | ((u32)l[1] << 16), (u32)l[2] | ((u32)l[3] << 16));
        if (i < XN4) { ((uint2*)g_xh)[i] = ph; ((uint2*)g_xl)[i] = pl; }
        else         { ((uint2*)g_wh)[i - XN4] = ph; ((uint2*)g_wl)[i - XN4] = pl; }
    }
}

// ================= Kernel 1: A = x @ Wa^T + ba via mma.sync (unchanged) =================
__global__ void __launch_bounds__(256, 2) xa_mma_kernel(const float* __restrict__ ba)
{
    extern __shared__ char xsm[];
    u32 base = (smem_u32(xsm) + 1023u) & ~1023u;
    const int tid = threadIdx.x, wid = tid >> 5, lan = tid & 31;
    const int nb64 = blockIdx.x * 64, mb = blockIdx.y;

    int srcA[4]; u32 dstA[4];
#pragma unroll
    for (int j = 0; j < 4; j++) {
        int e = tid + j * 256, row = e >> 3, k8 = (e & 7) * 8;
        srcA[j] = (mb * 128 + row) * HDIM + k8;
        dstA[j] = swz64(row, k8);
    }
    int srcB[2]; u32 dstB[2];
#pragma unroll
    for (int j = 0; j < 2; j++) {
        int e = tid + j * 256, row = e >> 3, k8 = (e & 7) * 8;
        srcB[j] = (nb64 + row) * HDIM + k8;
        dstB[j] = swz64(row, k8);
    }
    const int arow = wid * 16 + (lan & 15), acb = (lan >> 4) * 8;
    u32 aoff[4];
#pragma unroll
    for (int k16 = 0; k16 < 4; k16++) aoff[k16] = swz64(arow, k16 * 16 + acb);
    const int grp = lan >> 3;
    u32 boff[4][4];
#pragma unroll
    for (int jp = 0; jp < 4; jp++) {
        int nrow = (2 * jp + (grp >> 1)) * 8 + (lan & 7);
        int kc8 = (grp & 1) * 8;
#pragma unroll
        for (int k16 = 0; k16 < 4; k16++) boff[jp][k16] = swz64(nrow, k16 * 16 + kc8);
    }

    float c[32];
#pragma unroll
    for (int i = 0; i < 32; i++) c[i] = 0.0f;

#define XA_STAGE(bb, so) do {                                             \
    _Pragma("unroll")                                                     \
    for (int j = 0; j < 4; j++) {                                         \
        cpa16((bb) + dstA[j], g_xh + srcA[j] + (so));                     \
        cpa16((bb) + XA_ALO + dstA[j], g_xl + srcA[j] + (so));            \
    }                                                                     \
    _Pragma("unroll")                                                     \
    for (int j = 0; j < 2; j++) {                                         \
        cpa16((bb) + XA_BHI + dstB[j], g_wh + srcB[j] + (so));            \
        cpa16((bb) + XA_BLO + dstB[j], g_wl + srcB[j] + (so));            \
    }                                                                     \
    CP_COMMIT(); } while (0)

    XA_STAGE(base, 0);
    for (int kc = 0; kc < 16; kc++) {
        if (kc < 15) { XA_STAGE(base + ((kc + 1) & 1) * XA_BUF, (kc + 1) * 64); CP_WAIT1(); }
        else         { CP_WAIT0(); }
        __syncthreads();
        const u32 ah = base + (kc & 1) * XA_BUF;
        const u32 al = ah + XA_ALO, bh = ah + XA_BHI, bl = ah + XA_BLO;
#pragma unroll
        for (int k16 = 0; k16 < 4; k16++) {
            u32 a0, a1, a2, a3, l0, l1, l2, l3;
            ldsm_x4(ah + aoff[k16], a0, a1, a2, a3);
            ldsm_x4(al + aoff[k16], l0, l1, l2, l3);
#pragma unroll
            for (int jp = 0; jp < 4; jp++) {
                u32 h0, h1, h2, h3, q0, q1, q2, q3;
                ldsm_x4(bh + boff[jp][k16], h0, h1, h2, h3);
                ldsm_x4(bl + boff[jp][k16], q0, q1, q2, q3);
                float* c0 = c + (2 * jp) * 4;
                float* c1 = c + (2 * jp + 1) * 4;
                mma_bf16(c0, a0, a1, a2, a3, h0, h1);
                mma_bf16(c0, a0, a1, a2, a3, q0, q1);
                mma_bf16(c0, l0, l1, l2, l3, h0, h1);
                mma_bf16(c1, a0, a1, a2, a3, h2, h3);
                mma_bf16(c1, a0, a1, a2, a3, q2, q3);
                mma_bf16(c1, l0, l1, l2, l3, h2, h3);
            }
        }
        __syncthreads();
    }
#pragma unroll
    for (int nt = 0; nt < 8; nt++) {
        int col = nb64 + nt * 8 + (lan & 3) * 2;
        float2 bav = *(const float2*)(ba + col);
        int r0 = mb * 128 + wid * 16 + (lan >> 2);
        *(float2*)&g_A[((size_t)(r0 & 511) * BDIM + (r0 >> 9)) * HDIM + col] =
            make_float2(c[nt * 4 + 0] + bav.x, c[nt * 4 + 1] + bav.y);
        int r1 = r0 + 8;
        *(float2*)&g_A[((size_t)(r1 & 511) * BDIM + (r1 >> 9)) * HDIM + col] =
            make_float2(c[nt * 4 + 2] + bav.x, c[nt * 4 + 3] + bav.y);
    }
}

// ================= Kernel 2: persistent recurrence =================
// Warps 0-3 consumers, warps 4-7 producers. FULL ids 2..4, FREE ids 5..7 (cnt 256).
// Counters count 64 signals/CTA/step (per-thread red.release) -> need 1024/step.
// ds double-buffered by step parity: only ONE consumer barrier per step.
__global__ void __launch_bounds__(RTHREADS, 1) recur_mma_kernel(
    const float* __restrict__ Wmu,  const float* __restrict__ bmu,
    const float* __restrict__ Wgmu, const float* __restrict__ bgmu,
    const float* __restrict__ Wga,  const float* __restrict__ bga,
    float* __restrict__ out)
{
    extern __shared__ char smem_raw[];
    u32 raw_base = smem_u32(smem_raw);
    u32 abase = (raw_base + 1023u) & ~1023u;
    char* sm = smem_raw + (abase - raw_base);

    const int tid = threadIdx.x, wid = tid >> 5, lan = tid & 31;
    const int cta = blockIdx.x, nb = cta * NB;

    // ---- stage weights (resident all 512 steps) ----
    for (int u = tid; u < 24 * 128; u += RTHREADS) {
        int r = u >> 7, k = (u & 127) * 8;
        int g = r >> 3, nl = r & 7;
        const float* wp = (g == 0 ? Wmu : (g == 1 ? Wgmu : Wga)) + (size_t)(nb + nl) * HDIM + k;
        float4 v0 = *(const float4*)wp;
        float4 v1 = *(const float4*)(wp + 4);
        float vv[8] = {v0.x, v0.y, v0.z, v0.w, v1.x, v1.y, v1.z, v1.w};
        u32 hw[4], lw[4];
#pragma unroll
        for (int i = 0; i < 4; i++) {
            unsigned short h0 = f2bf(vv[2*i]),   h1 = f2bf(vv[2*i+1]);
            unsigned short l0 = f2bf(vv[2*i]   - bf2f(h0));
            unsigned short l1 = f2bf(vv[2*i+1] - bf2f(h1));
            hw[i] = (u32)h0 | ((u32)h1 << 16);
            lw[i] = (u32)l0 | ((u32)l1 << 16);
        }
        u32 byte = (u32)(k >> 6) * 3072u + (u32)g * 1024u + (u32)(r & 7) * 128u + (u32)(k & 63) * 2u;
        u32 sw = byte ^ ((u32)(r & 7) << 4);
        *(uint4*)(sm + OFF_WHI + sw) = make_uint4(hw[0], hw[1], hw[2], hw[3]);
        *(uint4*)(sm + OFF_WLO + sw) = make_uint4(lw[0], lw[1], lw[2], lw[3]);
    }
    if (tid < 64) {   // h0 = 0; each thread signals its own zero-stores
        uint4 z = make_uint4(0, 0, 0, 0);
        *(uint4*)&g_hh[0][tid * HDIM + nb] = z;
        *(uint4*)&g_hl[0][tid * HDIM + nb] = z;
        red_rel(&g_ready[cta >> 4][0]);
    }
    __syncthreads();

    const u32 hsb = abase + OFF_RING, whib = abase + OFF_WHI, wlob = abase + OFF_WLO;

    if (wid >= 4) {
        // ================== PRODUCER ==================
        const int ptid = tid & 127;
        int srcOff[8]; u32 dstOff[8];
#pragma unroll
        for (int j = 0; j < 8; j++) {
            int e = ptid + j * 128, row = e >> 4, k = (e & 15) * 8;
            srcOff[j] = row * HDIM + k;
            dstOff[j] = swzA(row, k);
        }
#define ISSUE_CHUNK(hhp, hlp, sb, so) do {                                  \
    _Pragma("unroll")                                                       \
    for (int j = 0; j < 8; j++) {                                           \
        cpa16((sb) + dstOff[j], (hhp) + srcOff[j] + (so));                  \
        cpa16((sb) + 16384 + dstOff[j], (hlp) + srcOff[j] + (so));          \
    }                                                                       \
    CP_COMMIT(); } while (0)

        wait_cnt_w(0, 1024u, lan);
        ISSUE_CHUNK(g_hh[0], g_hl[0], hsb, 0);
        wait_cnt_w(1, 1024u, lan);
        ISSUE_CHUNK(g_hh[0], g_hl[0], hsb + SLOT_SZ, KCH);

        int sig = 0, sig_sl = 0, m_sl = 2;
        for (int m = 2; m <= NTOT; m++) {
            if ((m & 7) == 0 || m == NTOT) {
                CP_WAIT0();                     // drain fully, signal all before blocking
                while (sig < m) {
                    bar_arrive_id(2 + sig_sl, 256);
                    sig++; if (++sig_sl == 3) sig_sl = 0;
                }
            } else {
                CP_WAIT1();
                if (sig < m - 1) {
                    bar_arrive_id(2 + sig_sl, 256);
                    sig++; if (++sig_sl == 3) sig_sl = 0;
                }
            }
            if (m == NTOT) break;
            if (m >= 3) bar_sync_id(5 + m_sl, 256);        // consumer freed chunk m-3
            int tm = m >> 3, cm = m & 7;
            wait_cnt_w(cm, 1024u * (u32)(tm + 1), lan);
            ISSUE_CHUNK(g_hh[tm & 1], g_hl[tm & 1], hsb + (u32)m_sl * SLOT_SZ, cm * KCH);
            if (++m_sl == 3) m_sl = 0;
        }
    } else {
        // ================== CONSUMER (packed-B + A double-buffer) ==================
        const int mt = wid;
        const int l15 = lan & 15, aklp = (lan >> 4) * 8;
        const int mi = lan >> 3, r7 = lan & 7;
        const u32 bbase = (mi < 2) ? whib : wlob;        // lanes 0-15 Whi, 16-31 Wlo
        u32 a_off[8], b_inn[8];
#pragma unroll
        for (int kl = 0; kl < 8; kl++) {
            a_off[kl] = swzA(mt * 16 + l15, kl * 16 + aklp);
            int bc = kl * 16 + (mi & 1) * 8;
            b_inn[kl] = ((u32)(bc >> 6) * 3072u + (u32)r7 * 128u + (u32)(bc & 63) * 2u)
                        ^ ((u32)r7 << 4);
        }
        float* ds = (float*)(sm + OFF_D);
        float cb_mu[8], cb_gm[8], cb_ga[8];
#pragma unroll
        for (int i = 0; i < 8; i++) {
            cb_mu[i] = bmu[nb + i]; cb_gm[i] = bgmu[nb + i]; cb_ga[i] = bga[nb + i];
        }

        int sl = 0;
        for (int t = 0; t < TSTEPS; t++) {
            float c[12];
#pragma unroll
            for (int i = 0; i < 12; i++) c[i] = 0.0f;
            float4 ga0 = make_float4(0, 0, 0, 0), ga1 = ga0;

            for (int kc = 0; kc < NCHUNK; kc++) {
                bar_sync_id(2 + sl, 256);                   // slot full
                if (kc == 4 && tid < 64) {                  // epilogue data prefetch
                    const float* ap = g_A + ((size_t)t * BDIM + tid) * HDIM + nb;
                    ga0 = __ldcg((const float4*)ap);
                    ga1 = __ldcg((const float4*)(ap + 4));
                }
                const u32 ahb = hsb + (u32)sl * SLOT_SZ, alb = ahb + 16384;
                const u32 wko = (u32)kc * 6144u;
                u32 Ah[2][4], Al[2][4];
                ldsm_x4(ahb + a_off[0], Ah[0][0], Ah[0][1], Ah[0][2], Ah[0][3]);
                ldsm_x4(alb + a_off[0], Al[0][0], Al[0][1], Al[0][2], Al[0][3]);
#pragma unroll
                for (int kl = 0; kl < 8; kl++) {
                    const int cur = kl & 1, nxt = cur ^ 1;
                    if (kl < 7) {                           // prefetch next A under this kl's MMAs
                        ldsm_x4(ahb + a_off[kl + 1], Ah[nxt][0], Ah[nxt][1], Ah[nxt][2], Ah[nxt][3]);
                        ldsm_x4(alb + a_off[kl + 1], Al[nxt][0], Al[nxt][1], Al[nxt][2], Al[nxt][3]);
                    }
#pragma unroll
                    for (int g = 0; g < 3; g++) {
                        u32 bh0, bh1, bl0, bl1;
                        ldsm_x4(bbase + wko + (u32)g * 1024u + b_inn[kl], bh0, bh1, bl0, bl1);
                        mma_bf16(c + g * 4, Ah[cur][0], Ah[cur][1], Ah[cur][2], Ah[cur][3], bh0, bh1);
                        mma_bf16(c + g * 4, Ah[cur][0], Ah[cur][1], Ah[cur][2], Ah[cur][3], bl0, bl1);
                        mma_bf16(c + g * 4, Al[cur][0], Al[cur][1], Al[cur][2], Al[cur][3], bh0, bh1);
                    }
                }
                bar_arrive_id(5 + sl, 256);                 // slot free
                if (++sl == 3) sl = 0;
            }

            // ---- D exchange (parity buffer) + single barrier + epilogue ----
            float* dsw = ds + (t & 1) * DSZ;
            int r0 = mt * 16 + (lan >> 2), cc = (lan & 3) * 2;
#pragma unroll
            for (int g = 0; g < 3; g++) {
                *(float2*)&dsw[r0 * DS_STRIDE + g * 8 + cc]       = make_float2(c[g*4+0], c[g*4+1]);
                *(float2*)&dsw[(r0 + 8) * DS_STRIDE + g * 8 + cc] = make_float2(c[g*4+2], c[g*4+3]);
            }
            bar_sync_id(1, 128);
            if (tid < 64) {
                const float* drow = dsw + tid * DS_STRIDE;
                float av[8] = {ga0.x, ga0.y, ga0.z, ga0.w, ga1.x, ga1.y, ga1.z, ga1.w};
                float ov[8];
#pragma unroll
                for (int i = 0; i < 8; i++) {
                    float mu = drow[i] + cb_mu[i];
                    float gm = drow[8 + i] + cb_gm[i];
                    float ga = drow[16 + i] + cb_ga[i];
                    ov[i] = mu * sigf(gm) + av[i] * sigf(ga);
                }
                u32 hw[4], lw[4];
#pragma unroll
                for (int i = 0; i < 4; i++) {
                    unsigned short h0 = f2bf(ov[2*i]),   h1 = f2bf(ov[2*i+1]);
                    unsigned short l0 = f2bf(ov[2*i]   - bf2f(h0));
                    unsigned short l1 = f2bf(ov[2*i+1] - bf2f(h1));
                    hw[i] = (u32)h0 | ((u32)h1 << 16);
                    lw[i] = (u32)l0 | ((u32)l1 << 16);
                }
                __stcg((uint4*)&g_hh[(t + 1) & 1][tid * HDIM + nb], make_uint4(hw[0], hw[1], hw[2], hw[3]));
                __stcg((uint4*)&g_hl[(t + 1) & 1][tid * HDIM + nb], make_uint4(lw[0], lw[1], lw[2], lw[3]));
                red_rel(&g_ready[cta >> 4][0]);             // per-thread release signal
                if (t == TSTEPS - 1) {
                    *(float4*)(out + (size_t)tid * HDIM + nb)     = make_float4(ov[0], ov[1], ov[2], ov[3]);
                    *(float4*)(out + (size_t)tid * HDIM + nb + 4) = make_float4(ov[4], ov[5], ov[6], ov[7]);
                }
            }
            // no second barrier: ds is parity-double-buffered, signal is per-thread
        }
    }
}

// ================= launch =================
extern "C" void kernel_launch(void* const* d_in, const int* in_sizes, int n_in,
                              void* d_out, int out_size) {
    const float* x    = (const float*)d_in[0];
    const float* Wmu  = (const float*)d_in[1];
    const float* bmu  = (const float*)d_in[2];
    const float* Wgmu = (const float*)d_in[3];
    const float* bgmu = (const float*)d_in[4];
    const float* Wa   = (const float*)d_in[5];
    const float* ba   = (const float*)d_in[6];
    const float* Wga  = (const float*)d_in[7];
    const float* bga  = (const float*)d_in[8];
    float* out = (float*)d_out;

    conv_kernel<<<2048, 256>>>(x, Wa);

    cudaFuncSetAttribute(xa_mma_kernel, cudaFuncAttributeMaxDynamicSharedMemorySize, XA_SMEM);
    xa_mma_kernel<<<dim3(16, 256), 256, XA_SMEM>>>(ba);

    cudaFuncSetAttribute(recur_mma_kernel, cudaFuncAttributeMaxDynamicSharedMemorySize, SMEM_TOTAL);
    recur_mma_kernel<<<NCTA, RTHREADS, SMEM_TOTAL>>>(Wmu, bmu, Wgmu, bgmu, Wga, bga, out);
}